// round 2
// baseline (speedup 1.0000x reference)
#include <cuda_runtime.h>
#include <math.h>

#define FF 64
#define KK 4
#define NMAX 100000
#define EMAX 1000000

// ---- scratch (static device globals; no allocation) ----
__device__ float g_xs[3][(size_t)NMAX * FF];   // xs[1..3]
__device__ float g_qsum[KK * FF];              // column sums of raw bases
__device__ float g_coef[9];                    // per-L combine coefficients
__device__ float g_Mt[KK * FF * FF];           // M[k][f][o] = sum_j Wfc[o,j]*Watt[k,j,f]
__device__ float g_wq[KK * FF];                // wq[k][f] = sum_j q[k,j]*Watt[k,j,f]
__device__ float g_qb[KK];
__device__ float g_mb[KK * FF];                // mb[k][o] = sum_j Wfc[o,j]*batt[k,j]
__device__ float g_att[(size_t)KK * NMAX];     // softmax attention weights [k][n]

// ---------------- coefficients + qsum zero ----------------
__global__ void k_coeff(const float* __restrict__ araw) {
    int t = threadIdx.x;
    if (t < KK * FF) g_qsum[t] = 0.f;
    if (t == 0) {
        float al[KK];
        #pragma unroll
        for (int i = 0; i < KK; i++) al[i] = tanhf(araw[i]);
        const float a = 1.f, b = 1.f, l = -1.f, r = 1.f;
        float coef1 = (a - b) * 0.5f - (a + b + 2.f) * 0.5f * (l + r) / (r - l);
        float coef2 = (a + b + 2.f) / (r - l);
        g_coef[0] = al[0] * coef2;  // multiplies adj result
        g_coef[1] = al[0] * coef1;  // multiplies x
        g_coef[2] = 0.f;
        for (int L = 2; L <= 3; L++) {
            float Lf = (float)L;
            float coef_l     = 2.f * Lf * (Lf + a + b) * (2.f * Lf - 2.f + a + b);
            float coef_lm1_1 = (2.f * Lf + a + b - 1.f) * (2.f * Lf + a + b) * (2.f * Lf + a + b - 2.f);
            float coef_lm1_2 = (2.f * Lf + a + b - 1.f) * (a * a - b * b);
            float coef_lm2   = 2.f * (Lf - 1.f + a) * (Lf - 1.f + b) * (2.f * Lf + a + b);
            float t1 = al[L - 1] * (coef_lm1_1 / coef_l);
            float t2 = al[L - 1] * (coef_lm1_2 / coef_l);
            float t3 = al[L - 1] * al[L - 2] * (coef_lm2 / coef_l);
            float t1_2 = t1 * (2.f / (r - l));
            float t2_2 = t1 * ((r + l) / (r - l)) + t2;
            g_coef[(L - 1) * 3 + 0] = t1_2;
            g_coef[(L - 1) * 3 + 1] = -t2_2;
            g_coef[(L - 1) * 3 + 2] = -t3;
        }
    }
}

// ---------------- zero xs buffers ----------------
__global__ void k_zero(long n4total) {
    long i = (long)blockIdx.x * blockDim.x + threadIdx.x;
    long stride = (long)gridDim.x * blockDim.x;
    float4* p = (float4*)&g_xs[0][0];
    float4 z = make_float4(0.f, 0.f, 0.f, 0.f);
    for (; i < n4total; i += stride) p[i] = z;
}

// ---------------- column sum of x into qsum[row] ----------------
__global__ void k_colsum(const float* __restrict__ src, long n4, int qrow) {
    __shared__ float bsum[FF];
    int t = threadIdx.x;
    if (t < FF) bsum[t] = 0.f;
    __syncthreads();
    long i = (long)blockIdx.x * blockDim.x + t;
    long stride = (long)gridDim.x * blockDim.x;  // multiple of 16 -> f0 invariant
    int f0 = (4 * t) & 63;
    float s0 = 0, s1 = 0, s2 = 0, s3 = 0;
    for (; i < n4; i += stride) {
        float4 v = ((const float4*)src)[i];
        s0 += v.x; s1 += v.y; s2 += v.z; s3 += v.w;
    }
    atomicAdd(&bsum[f0 + 0], s0);
    atomicAdd(&bsum[f0 + 1], s1);
    atomicAdd(&bsum[f0 + 2], s2);
    atomicAdd(&bsum[f0 + 3], s3);
    __syncthreads();
    if (t < FF) atomicAdd(&g_qsum[qrow * FF + t], bsum[t]);
}

// ---------------- edge scatter: acc[dst] += w * v[src] ----------------
// 16 threads per edge; lanes 0 and 16 load the edge record, broadcast via shfl.
__global__ void k_scatter(const int* __restrict__ ei, const float* __restrict__ ew,
                          const float* __restrict__ x, int vsel, int accsel, int E) {
    const float* v = (vsel < 0) ? x : &g_xs[vsel][0];
    float* acc = &g_xs[accsel][0];
    long t = (long)blockIdx.x * blockDim.x + threadIdx.x;
    int e = (int)(t >> 4);
    bool ok = e < E;
    unsigned lane = threadIdx.x & 31u;
    int d = 0, s = 0;
    float w = 0.f;
    if (ok && ((lane & 15u) == 0u)) {
        d = __ldg(ei + e);
        s = __ldg(ei + E + e);
        w = __ldg(ew + e);
    }
    int srcl = (int)(lane & 16u);   // 0 for lanes 0-15, 16 for lanes 16-31
    d = __shfl_sync(0xffffffffu, d, srcl);
    s = __shfl_sync(0xffffffffu, s, srcl);
    w = __shfl_sync(0xffffffffu, w, srcl);
    if (ok) {
        int c = (int)(t & 15);
        float4 val = *(const float4*)(v + (size_t)s * FF + (c << 2));
        val.x *= w; val.y *= w; val.z *= w; val.w *= w;
        float* p = acc + (size_t)d * FF + (c << 2);
        asm volatile("red.global.add.v4.f32 [%0], {%1,%2,%3,%4};"
                     :: "l"(p), "f"(val.x), "f"(val.y), "f"(val.z), "f"(val.w)
                     : "memory");
    }
}

// ---------------- recurrence combine (in place) + column sums ----------------
__global__ void k_combine(const float* __restrict__ x, int accsel, int m1sel, int m2sel,
                          long n4, int L) {
    __shared__ float bsum[FF];
    int t = threadIdx.x;
    if (t < FF) bsum[t] = 0.f;
    __syncthreads();
    const float* xm1 = (m1sel < 0) ? x : &g_xs[m1sel][0];
    const float* xm2 = (m2sel < 0) ? x : &g_xs[m2sel][0];
    float* acc = &g_xs[accsel][0];
    float cA = g_coef[(L - 1) * 3 + 0];
    float cB = g_coef[(L - 1) * 3 + 1];
    float cC = g_coef[(L - 1) * 3 + 2];
    long i = (long)blockIdx.x * blockDim.x + t;
    long stride = (long)gridDim.x * blockDim.x;
    int f0 = (4 * t) & 63;
    float s0 = 0, s1 = 0, s2 = 0, s3 = 0;
    for (; i < n4; i += stride) {
        float4 a  = ((float4*)acc)[i];
        float4 m1 = ((const float4*)xm1)[i];
        float4 m2 = ((const float4*)xm2)[i];
        float4 o;
        o.x = cA * a.x + cB * m1.x + cC * m2.x;
        o.y = cA * a.y + cB * m1.y + cC * m2.y;
        o.z = cA * a.z + cB * m1.z + cC * m2.z;
        o.w = cA * a.w + cB * m1.w + cC * m2.w;
        ((float4*)acc)[i] = o;
        s0 += o.x; s1 += o.y; s2 += o.z; s3 += o.w;
    }
    atomicAdd(&bsum[f0 + 0], s0);
    atomicAdd(&bsum[f0 + 1], s1);
    atomicAdd(&bsum[f0 + 2], s2);
    atomicAdd(&bsum[f0 + 3], s3);
    __syncthreads();
    if (t < FF) atomicAdd(&g_qsum[L * FF + t], bsum[t]);
}

// ---------------- prep 1: Mt[k][f][o] = sum_j Wfc[o,j]*Watt[k,j,f] ----------------
__global__ void k_prep1(const float* __restrict__ W_att, const float* __restrict__ W_fc) {
    __shared__ float wfcT[FF * FF];  // [j][o]
    int t = threadIdx.x;
    for (int i = t; i < FF * FF; i += 256) {
        int o = i >> 6, j = i & 63;
        wfcT[j * FF + o] = W_fc[i];
    }
    __syncthreads();
    // grid = 16 blocks, 4 iters each -> 16384 entries
    for (int it = 0; it < 4; it++) {
        int idx = it * 4096 + blockIdx.x * 256 + t;
        int k = idx >> 12;
        int rem = idx & 4095;
        int f = rem >> 6, o = rem & 63;
        float acc = 0.f;
        const float* wa = W_att + (k << 12) + f;  // wa[j*64]
        #pragma unroll
        for (int j = 0; j < FF; j++) acc += wfcT[j * FF + o] * __ldg(wa + (j << 6));
        g_Mt[(k << 12) + (f << 6) + o] = acc;
    }
}

// ---------------- prep 2: q, wq, qb, mb ----------------
__global__ void k_prep2(const float* __restrict__ W_att, const float* __restrict__ b_att,
                        const float* __restrict__ W_fc, int n) {
    __shared__ float q[KK * FF];
    int t = threadIdx.x;
    q[t] = g_qsum[t] * (1.0f / (float)n);
    __syncthreads();
    {   // wq
        int k = t >> 6, f = t & 63;
        float acc = 0.f;
        const float* wa = W_att + (k << 12) + f;
        #pragma unroll
        for (int j = 0; j < FF; j++) acc += q[(k << 6) + j] * __ldg(wa + (j << 6));
        g_wq[t] = acc;
    }
    {   // mb
        int k = t >> 6, o = t & 63;
        float acc = 0.f;
        const float* wf = W_fc + (o << 6);
        #pragma unroll
        for (int j = 0; j < FF; j++) acc += __ldg(wf + j) * __ldg(b_att + (k << 6) + j);
        g_mb[t] = acc;
    }
    if (t < KK) {
        float acc = 0.f;
        #pragma unroll
        for (int j = 0; j < FF; j++) acc += q[(t << 6) + j] * __ldg(b_att + (t << 6) + j);
        g_qb[t] = acc;
    }
}

// ---------------- logits + softmax over K ----------------
__global__ void k_logits(const float* __restrict__ x, int n) {
    __shared__ float rs[64 * 65];
    __shared__ float ss[KK][64];
    __shared__ float wqs[KK * FF];
    __shared__ float qbs[KK];
    int t = threadIdx.x;
    wqs[t] = g_wq[t];
    if (t < KK) qbs[t] = g_qb[t];
    for (int nb = blockIdx.x * 64; nb < n; nb += gridDim.x * 64) {
        for (int k = 0; k < KK; k++) {
            const float* src = (k == 0) ? x : &g_xs[k - 1][0];
            __syncthreads();
            for (int i = t; i < 64 * FF; i += 256) {
                int nn = i >> 6, f = i & 63;
                float v = (nb + nn < n) ? src[(size_t)(nb + nn) * FF + f] : 0.f;
                rs[nn * 65 + f] = v;
            }
            __syncthreads();
            if (t < 64) {
                float acc = qbs[k];
                #pragma unroll
                for (int f = 0; f < FF; f++) acc += wqs[k * FF + f] * rs[t * 65 + f];
                ss[k][t] = acc;
            }
        }
        __syncthreads();
        if (t < 64 && nb + t < n) {
            float s0 = tanhf(ss[0][t]), s1 = tanhf(ss[1][t]);
            float s2 = tanhf(ss[2][t]), s3 = tanhf(ss[3][t]);
            float m = fmaxf(fmaxf(s0, s1), fmaxf(s2, s3));
            float e0 = __expf(s0 - m), e1 = __expf(s1 - m);
            float e2 = __expf(s2 - m), e3 = __expf(s3 - m);
            float rinv = 1.f / (e0 + e1 + e2 + e3);
            size_t node = (size_t)(nb + t);
            g_att[0 * (size_t)n + node] = e0 * rinv;
            g_att[1 * (size_t)n + node] = e1 * rinv;
            g_att[2 * (size_t)n + node] = e2 * rinv;
            g_att[3 * (size_t)n + node] = e3 * rinv;
        }
    }
}

// ---------------- main fused attention GEMM ----------------
// out[n,o] = bfc[o] + sum_k att[k,n]*( mb[k,o] + sum_f M[k,f,o]*r[k,n,f] )
#define SM_MAIN_FLOATS (KK * FF * FF + FF * 68 + 256 + 256 + 64)
__global__ void k_main(const float* __restrict__ x, const float* __restrict__ b_fc,
                       float* __restrict__ out, int n) {
    extern __shared__ float sm[];
    float* Mts  = sm;                     // 16384  [k][f][o]
    float* rT   = Mts + KK * FF * FF;     // 64*68  [f][n] (att-scaled)
    float* atts = rT + FF * 68;           // 256    [k][n]
    float* mbs  = atts + 256;             // 256
    float* bfcs = mbs + 256;              // 64
    int t = threadIdx.x;
    for (int i = t; i < KK * FF * FF; i += 256) Mts[i] = g_Mt[i];
    mbs[t] = g_mb[t];
    if (t < FF) bfcs[t] = b_fc[t];
    __syncthreads();
    int tx = t & 15, ty = t >> 4;
    for (int nb = blockIdx.x * 64; nb < n; nb += gridDim.x * 64) {
        __syncthreads();  // guard atts/rT reuse vs previous epilogue
        for (int i = t; i < 256; i += 256) {
            int k = i >> 6, nn = i & 63;
            atts[i] = (nb + nn < n) ? g_att[(size_t)k * n + nb + nn] : 0.f;
        }
        float4 acc[4];
        #pragma unroll
        for (int i = 0; i < 4; i++) acc[i] = make_float4(0.f, 0.f, 0.f, 0.f);
        for (int k = 0; k < KK; k++) {
            const float* src = (k == 0) ? x : &g_xs[k - 1][0];
            __syncthreads();
            for (int i = t; i < FF * 64; i += 256) {
                int nn = i >> 6, f = i & 63;
                float v = (nb + nn < n) ? src[(size_t)(nb + nn) * FF + f] : 0.f;
                rT[f * 68 + nn] = v * atts[(k << 6) + nn];
            }
            __syncthreads();
            const float* Mk = Mts + (k << 12) + (tx << 2);
            #pragma unroll
            for (int f = 0; f < FF; f++) {
                float4 a = *(const float4*)(rT + f * 68 + (ty << 2));
                float4 b = *(const float4*)(Mk + (f << 6));
                acc[0].x += a.x * b.x; acc[0].y += a.x * b.y; acc[0].z += a.x * b.z; acc[0].w += a.x * b.w;
                acc[1].x += a.y * b.x; acc[1].y += a.y * b.y; acc[1].z += a.y * b.z; acc[1].w += a.y * b.w;
                acc[2].x += a.z * b.x; acc[2].y += a.z * b.y; acc[2].z += a.z * b.z; acc[2].w += a.z * b.w;
                acc[3].x += a.w * b.x; acc[3].y += a.w * b.y; acc[3].z += a.w * b.z; acc[3].w += a.w * b.w;
            }
        }
        #pragma unroll
        for (int i = 0; i < 4; i++) {
            int nn = (ty << 2) + i;
            int node = nb + nn;
            if (node < n) {
                float a0 = atts[nn], a1 = atts[64 + nn], a2 = atts[128 + nn], a3 = atts[192 + nn];
                int oc = tx << 2;
                float4 o4;
                o4.x = acc[i].x + bfcs[oc + 0] + a0 * mbs[oc + 0] + a1 * mbs[64 + oc + 0] + a2 * mbs[128 + oc + 0] + a3 * mbs[192 + oc + 0];
                o4.y = acc[i].y + bfcs[oc + 1] + a0 * mbs[oc + 1] + a1 * mbs[64 + oc + 1] + a2 * mbs[128 + oc + 1] + a3 * mbs[192 + oc + 1];
                o4.z = acc[i].z + bfcs[oc + 2] + a0 * mbs[oc + 2] + a1 * mbs[64 + oc + 2] + a2 * mbs[128 + oc + 2] + a3 * mbs[192 + oc + 2];
                o4.w = acc[i].w + bfcs[oc + 3] + a0 * mbs[oc + 3] + a1 * mbs[64 + oc + 3] + a2 * mbs[128 + oc + 3] + a3 * mbs[192 + oc + 3];
                *(float4*)(out + (size_t)node * FF + oc) = o4;
            }
        }
    }
}

extern "C" void kernel_launch(void* const* d_in, const int* in_sizes, int n_in,
                              void* d_out, int out_size) {
    const float* x     = (const float*)d_in[0];
    const int*   ei    = (const int*)d_in[1];
    const float* ew    = (const float*)d_in[2];
    const float* araw  = (const float*)d_in[3];
    const float* W_att = (const float*)d_in[4];
    const float* b_att = (const float*)d_in[5];
    const float* W_fc  = (const float*)d_in[6];
    const float* b_fc  = (const float*)d_in[7];
    float* out = (float*)d_out;

    int n = in_sizes[0] / FF;
    int E = in_sizes[2];
    long n4  = (long)n * FF / 4;       // float4 count per buffer
    long z4  = (long)3 * NMAX * FF / 4;

    cudaFuncSetAttribute(k_main, cudaFuncAttributeMaxDynamicSharedMemorySize,
                         SM_MAIN_FLOATS * sizeof(float));

    int scat_blocks = (int)(((long)E * 16 + 255) / 256);
    int tile_blocks = (n + 63) / 64;

    k_coeff<<<1, 256>>>(araw);
    k_zero<<<2048, 256>>>(z4);
    k_colsum<<<1024, 256>>>(x, n4, 0);
    // L = 1
    k_scatter<<<scat_blocks, 256>>>(ei, ew, x, -1, 0, E);
    k_combine<<<2048, 256>>>(x, 0, -1, -1, n4, 1);
    // L = 2
    k_scatter<<<scat_blocks, 256>>>(ei, ew, x, 0, 1, E);
    k_combine<<<2048, 256>>>(x, 1, 0, -1, n4, 2);
    // L = 3
    k_scatter<<<scat_blocks, 256>>>(ei, ew, x, 1, 2, E);
    k_combine<<<2048, 256>>>(x, 2, 1, 0, n4, 3);
    // attention prep + fused output
    k_prep1<<<16, 256>>>(W_att, W_fc);
    k_prep2<<<1, 256>>>(W_att, b_att, W_fc, n);
    k_logits<<<tile_blocks, 256>>>(x, n);
    k_main<<<tile_blocks, 256, SM_MAIN_FLOATS * sizeof(float)>>>(x, b_fc, out, n);
}

// round 4
// speedup vs baseline: 1.1708x; 1.1708x over previous
#include <cuda_runtime.h>
#include <math.h>

#define FF 64
#define KK 4
#define NMAX 100000
#define EMAX 1000000

// ---- scratch (static device globals; no allocation) ----
__device__ float g_xs[3][(size_t)NMAX * FF];   // bases xs[1..3]
__device__ float g_qsum[KK * FF];              // column sums of raw bases
__device__ float g_coef[9];                    // per-L combine coefficients
__device__ float g_Mt[KK * FF * FF];           // M[k][f][o] = sum_j Wfc[o,j]*Watt[k,j,f]
__device__ float g_wq[KK * FF];                // wq[k][f] = sum_j q[k,j]*Watt[k,j,f]
__device__ float g_qb[KK];
__device__ float g_mb[KK * FF];                // mb[k][o] = sum_j Wfc[o,j]*batt[k,j]
__device__ float g_att[(size_t)KK * NMAX];     // softmax attention weights [k][n]
// CSR scratch
__device__ int  g_deg[NMAX];
__device__ int  g_rptr[NMAX];                  // after fill: END pointer per row
__device__ int  g_bsums[256];                  // scan block partials
__device__ int2 g_csr[EMAX];                   // {src, weight_bits}

// ---------------- coefficients + qsum zero ----------------
__global__ void k_coeff(const float* __restrict__ araw) {
    int t = threadIdx.x;
    if (t < KK * FF) g_qsum[t] = 0.f;
    if (t == 0) {
        float al[KK];
        #pragma unroll
        for (int i = 0; i < KK; i++) al[i] = tanhf(araw[i]);
        const float a = 1.f, b = 1.f, l = -1.f, r = 1.f;
        float coef1 = (a - b) * 0.5f - (a + b + 2.f) * 0.5f * (l + r) / (r - l);
        float coef2 = (a + b + 2.f) / (r - l);
        g_coef[0] = al[0] * coef2;  // cA: multiplies pulled sum
        g_coef[1] = al[0] * coef1;  // cB: multiplies m1 (= x)
        g_coef[2] = 0.f;            // cC
        for (int L = 2; L <= 3; L++) {
            float Lf = (float)L;
            float coef_l     = 2.f * Lf * (Lf + a + b) * (2.f * Lf - 2.f + a + b);
            float coef_lm1_1 = (2.f * Lf + a + b - 1.f) * (2.f * Lf + a + b) * (2.f * Lf + a + b - 2.f);
            float coef_lm1_2 = (2.f * Lf + a + b - 1.f) * (a * a - b * b);
            float coef_lm2   = 2.f * (Lf - 1.f + a) * (Lf - 1.f + b) * (2.f * Lf + a + b);
            float t1 = al[L - 1] * (coef_lm1_1 / coef_l);
            float t2 = al[L - 1] * (coef_lm1_2 / coef_l);
            float t3 = al[L - 1] * al[L - 2] * (coef_lm2 / coef_l);
            float t1_2 = t1 * (2.f / (r - l));
            float t2_2 = t1 * ((r + l) / (r - l)) + t2;
            g_coef[(L - 1) * 3 + 0] = t1_2;
            g_coef[(L - 1) * 3 + 1] = -t2_2;
            g_coef[(L - 1) * 3 + 2] = -t3;
        }
    }
}

// ---------------- CSR build ----------------
__global__ void k_zero_deg(int n) {
    int i = blockIdx.x * blockDim.x + threadIdx.x;
    if (i < n) g_deg[i] = 0;
}

__global__ void k_hist(const int* __restrict__ ei, int E) {
    int e = blockIdx.x * blockDim.x + threadIdx.x;
    if (e < E) atomicAdd(&g_deg[ei[e]], 1);
}

// per-block exclusive scan of deg -> g_rptr (local), block totals -> g_bsums
__global__ void k_scan1(int n) {
    __shared__ int s[1024];
    int t = threadIdx.x;
    int i = blockIdx.x * 1024 + t;
    int d = (i < n) ? g_deg[i] : 0;
    s[t] = d;
    __syncthreads();
    #pragma unroll
    for (int off = 1; off < 1024; off <<= 1) {
        int v = (t >= off) ? s[t - off] : 0;
        __syncthreads();
        s[t] += v;
        __syncthreads();
    }
    if (i < n) g_rptr[i] = s[t] - d;   // exclusive within block
    if (t == 1023) g_bsums[blockIdx.x] = s[1023];
}

// tiny serial exclusive scan of block partials
__global__ void k_scan2(int nb) {
    if (threadIdx.x == 0) {
        int run = 0;
        for (int b = 0; b < nb; b++) {
            int v = g_bsums[b];
            g_bsums[b] = run;
            run += v;
        }
    }
}

__global__ void k_scan3(int n) {
    int i = blockIdx.x * 1024 + threadIdx.x;
    if (i < n) g_rptr[i] += g_bsums[blockIdx.x];
}

// fill CSR; g_rptr becomes END pointer per row (start = end - deg)
__global__ void k_fill(const int* __restrict__ ei, const float* __restrict__ ew, int E) {
    int e = blockIdx.x * blockDim.x + threadIdx.x;
    if (e < E) {
        int dst = ei[e];
        int src = ei[E + e];
        float w = ew[e];
        int pos = atomicAdd(&g_rptr[dst], 1);
        g_csr[pos] = make_int2(src, __float_as_int(w));
    }
}

// ---------------- fused pull SpMM + recurrence + colsum ----------------
// acc[node] = cA * sum_j w_j*m1[src_j] + cB*m1[node] + cC*m2[node]
// also accumulates colsum of acc into qsum[L]; if do_row0, colsum of m1(=x) into qsum[0]
__global__ void k_pull(const float* __restrict__ x, int m1sel, int m2sel, int accsel,
                       int L, int n, int do_row0) {
    __shared__ float bsum[FF];
    __shared__ float bsum0[FF];
    int t = threadIdx.x;
    if (t < FF) { bsum[t] = 0.f; bsum0[t] = 0.f; }
    __syncthreads();
    const float* m1 = (m1sel < 0) ? x : &g_xs[m1sel][0];
    const float* m2 = (m2sel < 0) ? x : &g_xs[m2sel][0];
    float* acc = &g_xs[accsel][0];
    float cA = g_coef[(L - 1) * 3 + 0];
    float cB = g_coef[(L - 1) * 3 + 1];
    float cC = g_coef[(L - 1) * 3 + 2];
    int node = blockIdx.x * 16 + (t >> 4);
    int c4 = (t & 15) << 2;
    if (node < n) {
        int end = g_rptr[node];
        int deg = g_deg[node];
        int j = end - deg;
        float4 s = make_float4(0.f, 0.f, 0.f, 0.f);
        for (; j + 1 < end; j += 2) {
            int2 e0 = g_csr[j];
            int2 e1 = g_csr[j + 1];
            float w0 = __int_as_float(e0.y);
            float w1 = __int_as_float(e1.y);
            float4 a = *(const float4*)(m1 + (size_t)e0.x * FF + c4);
            float4 b = *(const float4*)(m1 + (size_t)e1.x * FF + c4);
            s.x += w0 * a.x + w1 * b.x;
            s.y += w0 * a.y + w1 * b.y;
            s.z += w0 * a.z + w1 * b.z;
            s.w += w0 * a.w + w1 * b.w;
        }
        if (j < end) {
            int2 e0 = g_csr[j];
            float w0 = __int_as_float(e0.y);
            float4 a = *(const float4*)(m1 + (size_t)e0.x * FF + c4);
            s.x += w0 * a.x;
            s.y += w0 * a.y;
            s.z += w0 * a.z;
            s.w += w0 * a.w;
        }
        float4 m1v = *(const float4*)(m1 + (size_t)node * FF + c4);
        float4 o;
        o.x = cA * s.x + cB * m1v.x;
        o.y = cA * s.y + cB * m1v.y;
        o.z = cA * s.z + cB * m1v.z;
        o.w = cA * s.w + cB * m1v.w;
        if (L >= 2) {
            float4 m2v = *(const float4*)(m2 + (size_t)node * FF + c4);
            o.x += cC * m2v.x;
            o.y += cC * m2v.y;
            o.z += cC * m2v.z;
            o.w += cC * m2v.w;
        }
        *(float4*)(acc + (size_t)node * FF + c4) = o;
        atomicAdd(&bsum[c4 + 0], o.x);
        atomicAdd(&bsum[c4 + 1], o.y);
        atomicAdd(&bsum[c4 + 2], o.z);
        atomicAdd(&bsum[c4 + 3], o.w);
        if (do_row0) {
            atomicAdd(&bsum0[c4 + 0], m1v.x);
            atomicAdd(&bsum0[c4 + 1], m1v.y);
            atomicAdd(&bsum0[c4 + 2], m1v.z);
            atomicAdd(&bsum0[c4 + 3], m1v.w);
        }
    }
    __syncthreads();
    if (t < FF) {
        atomicAdd(&g_qsum[L * FF + t], bsum[t]);
        if (do_row0) atomicAdd(&g_qsum[t], bsum0[t]);
    }
}

// ---------------- prep 1: Mt[k][f][o] = sum_j Wfc[o,j]*Watt[k,j,f] ----------------
__global__ void k_prep1(const float* __restrict__ W_att, const float* __restrict__ W_fc) {
    __shared__ float wfcT[FF * FF];  // [j][o]
    int t = threadIdx.x;
    for (int i = t; i < FF * FF; i += 256) {
        int o = i >> 6, j = i & 63;
        wfcT[j * FF + o] = W_fc[i];
    }
    __syncthreads();
    for (int it = 0; it < 4; it++) {
        int idx = it * 4096 + blockIdx.x * 256 + t;
        int k = idx >> 12;
        int rem = idx & 4095;
        int f = rem >> 6, o = rem & 63;
        float acc = 0.f;
        const float* wa = W_att + (k << 12) + f;  // wa[j*64]
        #pragma unroll
        for (int j = 0; j < FF; j++) acc += wfcT[j * FF + o] * __ldg(wa + (j << 6));
        g_Mt[(k << 12) + (f << 6) + o] = acc;
    }
}

// ---------------- prep 2: q, wq, qb, mb ----------------
__global__ void k_prep2(const float* __restrict__ W_att, const float* __restrict__ b_att,
                        const float* __restrict__ W_fc, int n) {
    __shared__ float q[KK * FF];
    int t = threadIdx.x;
    q[t] = g_qsum[t] * (1.0f / (float)n);
    __syncthreads();
    {   // wq
        int k = t >> 6, f = t & 63;
        float acc = 0.f;
        const float* wa = W_att + (k << 12) + f;
        #pragma unroll
        for (int j = 0; j < FF; j++) acc += q[(k << 6) + j] * __ldg(wa + (j << 6));
        g_wq[t] = acc;
    }
    {   // mb
        int k = t >> 6, o = t & 63;
        float acc = 0.f;
        const float* wf = W_fc + (o << 6);
        #pragma unroll
        for (int j = 0; j < FF; j++) acc += __ldg(wf + j) * __ldg(b_att + (k << 6) + j);
        g_mb[t] = acc;
    }
    if (t < KK) {
        float acc = 0.f;
        #pragma unroll
        for (int j = 0; j < FF; j++) acc += q[(t << 6) + j] * __ldg(b_att + (t << 6) + j);
        g_qb[t] = acc;
    }
}

// ---------------- logits + softmax over K ----------------
__global__ void k_logits(const float* __restrict__ x, int n) {
    __shared__ float rs[64 * 65];
    __shared__ float ss[KK][64];
    __shared__ float wqs[KK * FF];
    __shared__ float qbs[KK];
    int t = threadIdx.x;
    wqs[t] = g_wq[t];
    if (t < KK) qbs[t] = g_qb[t];
    for (int nb = blockIdx.x * 64; nb < n; nb += gridDim.x * 64) {
        for (int k = 0; k < KK; k++) {
            const float* src = (k == 0) ? x : &g_xs[k - 1][0];
            __syncthreads();
            for (int i = t; i < 64 * FF; i += 256) {
                int nn = i >> 6, f = i & 63;
                float v = (nb + nn < n) ? src[(size_t)(nb + nn) * FF + f] : 0.f;
                rs[nn * 65 + f] = v;
            }
            __syncthreads();
            if (t < 64) {
                float acc = qbs[k];
                #pragma unroll
                for (int f = 0; f < FF; f++) acc += wqs[k * FF + f] * rs[t * 65 + f];
                ss[k][t] = acc;
            }
        }
        __syncthreads();
        if (t < 64 && nb + t < n) {
            float s0 = tanhf(ss[0][t]), s1 = tanhf(ss[1][t]);
            float s2 = tanhf(ss[2][t]), s3 = tanhf(ss[3][t]);
            float m = fmaxf(fmaxf(s0, s1), fmaxf(s2, s3));
            float e0 = __expf(s0 - m), e1 = __expf(s1 - m);
            float e2 = __expf(s2 - m), e3 = __expf(s3 - m);
            float rinv = 1.f / (e0 + e1 + e2 + e3);
            size_t node = (size_t)(nb + t);
            g_att[0 * (size_t)n + node] = e0 * rinv;
            g_att[1 * (size_t)n + node] = e1 * rinv;
            g_att[2 * (size_t)n + node] = e2 * rinv;
            g_att[3 * (size_t)n + node] = e3 * rinv;
        }
    }
}

// ---------------- main fused attention GEMM ----------------
// out[n,o] = bfc[o] + sum_k att[k,n]*( mb[k,o] + sum_f M[k,f,o]*r[k,n,f] )
#define SM_MAIN_FLOATS (KK * FF * FF + FF * 68 + 256 + 256 + 64)
__global__ void k_main(const float* __restrict__ x, const float* __restrict__ b_fc,
                       float* __restrict__ out, int n) {
    extern __shared__ float sm[];
    float* Mts  = sm;                     // 16384  [k][f][o]
    float* rT   = Mts + KK * FF * FF;     // 64*68  [f][n] (att-scaled)
    float* atts = rT + FF * 68;           // 256    [k][n]
    float* mbs  = atts + 256;             // 256
    float* bfcs = mbs + 256;              // 64
    int t = threadIdx.x;
    for (int i = t; i < KK * FF * FF; i += 256) Mts[i] = g_Mt[i];
    mbs[t] = g_mb[t];
    if (t < FF) bfcs[t] = b_fc[t];
    __syncthreads();
    int tx = t & 15, ty = t >> 4;
    for (int nb = blockIdx.x * 64; nb < n; nb += gridDim.x * 64) {
        __syncthreads();  // guard atts/rT reuse vs previous epilogue
        for (int i = t; i < 256; i += 256) {
            int k = i >> 6, nn = i & 63;
            atts[i] = (nb + nn < n) ? g_att[(size_t)k * n + nb + nn] : 0.f;
        }
        float4 acc[4];
        #pragma unroll
        for (int i = 0; i < 4; i++) acc[i] = make_float4(0.f, 0.f, 0.f, 0.f);
        for (int k = 0; k < KK; k++) {
            const float* src = (k == 0) ? x : &g_xs[k - 1][0];
            __syncthreads();
            for (int i = t; i < FF * 64; i += 256) {
                int nn = i >> 6, f = i & 63;
                float v = (nb + nn < n) ? src[(size_t)(nb + nn) * FF + f] : 0.f;
                rT[f * 68 + nn] = v * atts[(k << 6) + nn];
            }
            __syncthreads();
            const float* Mk = Mts + (k << 12) + (tx << 2);
            #pragma unroll
            for (int f = 0; f < FF; f++) {
                float4 a = *(const float4*)(rT + f * 68 + (ty << 2));
                float4 b = *(const float4*)(Mk + (f << 6));
                acc[0].x += a.x * b.x; acc[0].y += a.x * b.y; acc[0].z += a.x * b.z; acc[0].w += a.x * b.w;
                acc[1].x += a.y * b.x; acc[1].y += a.y * b.y; acc[1].z += a.y * b.z; acc[1].w += a.y * b.w;
                acc[2].x += a.z * b.x; acc[2].y += a.z * b.y; acc[2].z += a.z * b.z; acc[2].w += a.z * b.w;
                acc[3].x += a.w * b.x; acc[3].y += a.w * b.y; acc[3].z += a.w * b.z; acc[3].w += a.w * b.w;
            }
        }
        #pragma unroll
        for (int i = 0; i < 4; i++) {
            int nn = (ty << 2) + i;
            int node = nb + nn;
            if (node < n) {
                float a0 = atts[nn], a1 = atts[64 + nn], a2 = atts[128 + nn], a3 = atts[192 + nn];
                int oc = tx << 2;
                float4 o4;
                o4.x = acc[i].x + bfcs[oc + 0] + a0 * mbs[oc + 0] + a1 * mbs[64 + oc + 0] + a2 * mbs[128 + oc + 0] + a3 * mbs[192 + oc + 0];
                o4.y = acc[i].y + bfcs[oc + 1] + a0 * mbs[oc + 1] + a1 * mbs[64 + oc + 1] + a2 * mbs[128 + oc + 1] + a3 * mbs[192 + oc + 1];
                o4.z = acc[i].z + bfcs[oc + 2] + a0 * mbs[oc + 2] + a1 * mbs[64 + oc + 2] + a2 * mbs[128 + oc + 2] + a3 * mbs[192 + oc + 2];
                o4.w = acc[i].w + bfcs[oc + 3] + a0 * mbs[oc + 3] + a1 * mbs[64 + oc + 3] + a2 * mbs[128 + oc + 3] + a3 * mbs[192 + oc + 3];
                *(float4*)(out + (size_t)node * FF + oc) = o4;
            }
        }
    }
}

extern "C" void kernel_launch(void* const* d_in, const int* in_sizes, int n_in,
                              void* d_out, int out_size) {
    const float* x     = (const float*)d_in[0];
    const int*   ei    = (const int*)d_in[1];
    const float* ew    = (const float*)d_in[2];
    const float* araw  = (const float*)d_in[3];
    const float* W_att = (const float*)d_in[4];
    const float* b_att = (const float*)d_in[5];
    const float* W_fc  = (const float*)d_in[6];
    const float* b_fc  = (const float*)d_in[7];
    float* out = (float*)d_out;

    int n = in_sizes[0] / FF;
    int E = in_sizes[2];

    cudaFuncSetAttribute(k_main, cudaFuncAttributeMaxDynamicSharedMemorySize,
                         SM_MAIN_FLOATS * sizeof(float));

    int nb_scan = (n + 1023) / 1024;
    int eb = (E + 255) / 256;
    int nb256 = (n + 255) / 256;
    int pull_blocks = (n + 15) / 16;
    int tile_blocks = (n + 63) / 64;

    k_coeff<<<1, 256>>>(araw);
    // CSR build
    k_zero_deg<<<nb256, 256>>>(n);
    k_hist<<<eb, 256>>>(ei, E);
    k_scan1<<<nb_scan, 1024>>>(n);
    k_scan2<<<1, 32>>>(nb_scan);
    k_scan3<<<nb_scan, 1024>>>(n);
    k_fill<<<eb, 256>>>(ei, ew, E);
    // fused pull + recurrence + colsums
    k_pull<<<pull_blocks, 256>>>(x, -1,  -1, 0, 1, n, 1);   // L=1: m1=x (cC=0), row0 colsum
    k_pull<<<pull_blocks, 256>>>(x,  0,  -1, 1, 2, n, 0);   // L=2: m1=xs0, m2=x
    k_pull<<<pull_blocks, 256>>>(x,  1,   0, 2, 3, n, 0);   // L=3: m1=xs1, m2=xs0
    // attention prep + fused output
    k_prep1<<<16, 256>>>(W_att, W_fc);
    k_prep2<<<1, 256>>>(W_att, b_att, W_fc, n);
    k_logits<<<tile_blocks, 256>>>(x, n);
    k_main<<<tile_blocks, 256, SM_MAIN_FLOATS * sizeof(float)>>>(x, b_fc, out, n);
}

// round 5
// speedup vs baseline: 1.6000x; 1.3666x over previous
#include <cuda_runtime.h>
#include <math.h>

#define FF 64
#define KK 4
#define NMAX 100000
#define EMAX 1000000

// ---- scratch (static device globals; no allocation) ----
__device__ float g_xs[3][(size_t)NMAX * FF];   // bases xs[1..3]
__device__ float g_qsum[KK * FF];              // column sums of raw bases
__device__ float g_coef[9];                    // per-L combine coefficients
__device__ float g_Mt[KK * FF * FF];           // M[k][f][o] = sum_j Wfc[o,j]*Watt[k,j,f]
__device__ float g_wq[KK * FF];                // wq[k][f] = sum_j q[k,j]*Watt[k,j,f]
__device__ float g_qb[KK];
__device__ float g_mb[KK * FF];                // mb[k][o] = sum_j Wfc[o,j]*batt[k,j]
// CSR scratch
__device__ int  g_deg[NMAX];
__device__ int  g_rptr[NMAX];                  // after fill: END pointer per row
__device__ int  g_bsums[256];                  // scan block partials
__device__ int2 g_csr[EMAX];                   // {src, weight_bits}

// ---------------- coefficients + qsum zero ----------------
__global__ void k_coeff(const float* __restrict__ araw) {
    int t = threadIdx.x;
    if (t < KK * FF) g_qsum[t] = 0.f;
    if (t == 0) {
        float al[KK];
        #pragma unroll
        for (int i = 0; i < KK; i++) al[i] = tanhf(araw[i]);
        const float a = 1.f, b = 1.f, l = -1.f, r = 1.f;
        float coef1 = (a - b) * 0.5f - (a + b + 2.f) * 0.5f * (l + r) / (r - l);
        float coef2 = (a + b + 2.f) / (r - l);
        g_coef[0] = al[0] * coef2;  // cA
        g_coef[1] = al[0] * coef1;  // cB
        g_coef[2] = 0.f;            // cC
        for (int L = 2; L <= 3; L++) {
            float Lf = (float)L;
            float coef_l     = 2.f * Lf * (Lf + a + b) * (2.f * Lf - 2.f + a + b);
            float coef_lm1_1 = (2.f * Lf + a + b - 1.f) * (2.f * Lf + a + b) * (2.f * Lf + a + b - 2.f);
            float coef_lm1_2 = (2.f * Lf + a + b - 1.f) * (a * a - b * b);
            float coef_lm2   = 2.f * (Lf - 1.f + a) * (Lf - 1.f + b) * (2.f * Lf + a + b);
            float t1 = al[L - 1] * (coef_lm1_1 / coef_l);
            float t2 = al[L - 1] * (coef_lm1_2 / coef_l);
            float t3 = al[L - 1] * al[L - 2] * (coef_lm2 / coef_l);
            float t1_2 = t1 * (2.f / (r - l));
            float t2_2 = t1 * ((r + l) / (r - l)) + t2;
            g_coef[(L - 1) * 3 + 0] = t1_2;
            g_coef[(L - 1) * 3 + 1] = -t2_2;
            g_coef[(L - 1) * 3 + 2] = -t3;
        }
    }
}

// ---------------- CSR build ----------------
__global__ void k_zero_deg(int n) {
    int i = blockIdx.x * blockDim.x + threadIdx.x;
    if (i < n) g_deg[i] = 0;
}

__global__ void k_hist(const int* __restrict__ ei, int E) {
    int e = blockIdx.x * blockDim.x + threadIdx.x;
    if (e < E) atomicAdd(&g_deg[ei[e]], 1);
}

// per-block exclusive scan of deg -> g_rptr (local), block totals -> g_bsums
__global__ void k_scan1(int n) {
    __shared__ int s[1024];
    int t = threadIdx.x;
    int i = blockIdx.x * 1024 + t;
    int d = (i < n) ? g_deg[i] : 0;
    s[t] = d;
    __syncthreads();
    #pragma unroll
    for (int off = 1; off < 1024; off <<= 1) {
        int v = (t >= off) ? s[t - off] : 0;
        __syncthreads();
        s[t] += v;
        __syncthreads();
    }
    if (i < n) g_rptr[i] = s[t] - d;   // exclusive within block
    if (t == 1023) g_bsums[blockIdx.x] = s[1023];
}

// parallel exclusive scan of up to 256 block partials (one block)
__global__ void k_scan2(int nb) {
    __shared__ int s[256];
    int t = threadIdx.x;
    int v = (t < nb) ? g_bsums[t] : 0;
    s[t] = v;
    __syncthreads();
    #pragma unroll
    for (int off = 1; off < 256; off <<= 1) {
        int u = (t >= off) ? s[t - off] : 0;
        __syncthreads();
        s[t] += u;
        __syncthreads();
    }
    if (t < nb) g_bsums[t] = s[t] - v;  // exclusive
}

__global__ void k_scan3(int n) {
    int i = blockIdx.x * 1024 + threadIdx.x;
    if (i < n) g_rptr[i] += g_bsums[blockIdx.x];
}

// fill CSR; g_rptr becomes END pointer per row (start = end - deg)
__global__ void k_fill(const int* __restrict__ ei, const float* __restrict__ ew, int E) {
    int e = blockIdx.x * blockDim.x + threadIdx.x;
    if (e < E) {
        int dst = ei[e];
        int src = ei[E + e];
        float w = ew[e];
        int pos = atomicAdd(&g_rptr[dst], 1);
        g_csr[pos] = make_int2(src, __float_as_int(w));
    }
}

// ---------------- fused pull SpMM + recurrence + colsum ----------------
__global__ void k_pull(const float* __restrict__ x, int m1sel, int m2sel, int accsel,
                       int L, int n, int do_row0) {
    __shared__ float bsum[FF];
    __shared__ float bsum0[FF];
    int t = threadIdx.x;
    if (t < FF) { bsum[t] = 0.f; bsum0[t] = 0.f; }
    __syncthreads();
    const float* m1 = (m1sel < 0) ? x : &g_xs[m1sel][0];
    const float* m2 = (m2sel < 0) ? x : &g_xs[m2sel][0];
    float* acc = &g_xs[accsel][0];
    float cA = g_coef[(L - 1) * 3 + 0];
    float cB = g_coef[(L - 1) * 3 + 1];
    float cC = g_coef[(L - 1) * 3 + 2];
    int node = blockIdx.x * 16 + (t >> 4);
    int c4 = (t & 15) << 2;
    if (node < n) {
        int end = g_rptr[node];
        int deg = g_deg[node];
        int j = end - deg;
        float4 s = make_float4(0.f, 0.f, 0.f, 0.f);
        // 4-deep unroll for MLP
        for (; j + 3 < end; j += 4) {
            int2 e0 = g_csr[j];
            int2 e1 = g_csr[j + 1];
            int2 e2 = g_csr[j + 2];
            int2 e3 = g_csr[j + 3];
            float4 a0 = *(const float4*)(m1 + (size_t)e0.x * FF + c4);
            float4 a1 = *(const float4*)(m1 + (size_t)e1.x * FF + c4);
            float4 a2 = *(const float4*)(m1 + (size_t)e2.x * FF + c4);
            float4 a3 = *(const float4*)(m1 + (size_t)e3.x * FF + c4);
            float w0 = __int_as_float(e0.y), w1 = __int_as_float(e1.y);
            float w2 = __int_as_float(e2.y), w3 = __int_as_float(e3.y);
            s.x += w0 * a0.x + w1 * a1.x + w2 * a2.x + w3 * a3.x;
            s.y += w0 * a0.y + w1 * a1.y + w2 * a2.y + w3 * a3.y;
            s.z += w0 * a0.z + w1 * a1.z + w2 * a2.z + w3 * a3.z;
            s.w += w0 * a0.w + w1 * a1.w + w2 * a2.w + w3 * a3.w;
        }
        for (; j < end; j++) {
            int2 e0 = g_csr[j];
            float w0 = __int_as_float(e0.y);
            float4 a = *(const float4*)(m1 + (size_t)e0.x * FF + c4);
            s.x += w0 * a.x; s.y += w0 * a.y; s.z += w0 * a.z; s.w += w0 * a.w;
        }
        float4 m1v = *(const float4*)(m1 + (size_t)node * FF + c4);
        float4 o;
        o.x = cA * s.x + cB * m1v.x;
        o.y = cA * s.y + cB * m1v.y;
        o.z = cA * s.z + cB * m1v.z;
        o.w = cA * s.w + cB * m1v.w;
        if (L >= 2) {
            float4 m2v = *(const float4*)(m2 + (size_t)node * FF + c4);
            o.x += cC * m2v.x; o.y += cC * m2v.y; o.z += cC * m2v.z; o.w += cC * m2v.w;
        }
        *(float4*)(acc + (size_t)node * FF + c4) = o;
        atomicAdd(&bsum[c4 + 0], o.x);
        atomicAdd(&bsum[c4 + 1], o.y);
        atomicAdd(&bsum[c4 + 2], o.z);
        atomicAdd(&bsum[c4 + 3], o.w);
        if (do_row0) {
            atomicAdd(&bsum0[c4 + 0], m1v.x);
            atomicAdd(&bsum0[c4 + 1], m1v.y);
            atomicAdd(&bsum0[c4 + 2], m1v.z);
            atomicAdd(&bsum0[c4 + 3], m1v.w);
        }
    }
    __syncthreads();
    if (t < FF) {
        atomicAdd(&g_qsum[L * FF + t], bsum[t]);
        if (do_row0) atomicAdd(&g_qsum[t], bsum0[t]);
    }
}

// ---------------- prep 1: Mt[k][f][o] = sum_j Wfc[o,j]*Watt[k,j,f] ----------------
__global__ void k_prep1(const float* __restrict__ W_att, const float* __restrict__ W_fc) {
    __shared__ float wfcT[FF * FF];  // [j][o]
    int t = threadIdx.x;
    for (int i = t; i < FF * FF; i += 256) {
        int o = i >> 6, j = i & 63;
        wfcT[j * FF + o] = W_fc[i];
    }
    __syncthreads();
    for (int it = 0; it < 4; it++) {
        int idx = it * 4096 + blockIdx.x * 256 + t;
        int k = idx >> 12;
        int rem = idx & 4095;
        int f = rem >> 6, o = rem & 63;
        float acc = 0.f;
        const float* wa = W_att + (k << 12) + f;  // wa[j*64]
        #pragma unroll
        for (int j = 0; j < FF; j++) acc += wfcT[j * FF + o] * __ldg(wa + (j << 6));
        g_Mt[(k << 12) + (f << 6) + o] = acc;
    }
}

// ---------------- prep 2: q, wq, qb, mb ----------------
__global__ void k_prep2(const float* __restrict__ W_att, const float* __restrict__ b_att,
                        const float* __restrict__ W_fc, int n) {
    __shared__ float q[KK * FF];
    int t = threadIdx.x;
    q[t] = g_qsum[t] * (1.0f / (float)n);
    __syncthreads();
    {   // wq
        int k = t >> 6, f = t & 63;
        float acc = 0.f;
        const float* wa = W_att + (k << 12) + f;
        #pragma unroll
        for (int j = 0; j < FF; j++) acc += q[(k << 6) + j] * __ldg(wa + (j << 6));
        g_wq[t] = acc;
    }
    {   // mb
        int k = t >> 6, o = t & 63;
        float acc = 0.f;
        const float* wf = W_fc + (o << 6);
        #pragma unroll
        for (int j = 0; j < FF; j++) acc += __ldg(wf + j) * __ldg(b_att + (k << 6) + j);
        g_mb[t] = acc;
    }
    if (t < KK) {
        float acc = 0.f;
        #pragma unroll
        for (int j = 0; j < FF; j++) acc += q[(t << 6) + j] * __ldg(b_att + (t << 6) + j);
        g_qb[t] = acc;
    }
}

// ---------------- fused logits + softmax + attention GEMM ----------------
// Per 64-node tile, single pass over the 4 bases:
//   y_k = M_k r_k  (register accumulators, 4 sets)
//   s_k = tanh(qb_k + wq_k . r_k)     (from same smem tile)
// epilogue: att = softmax_k(s), out = bfc + sum_k att_k (y_k + mb_k)
#define SM_FUSED_FLOATS (KK * FF * FF + FF * 68 + KK * FF + KK * FF + FF + KK + KK * 64)
__global__ __launch_bounds__(256, 2)
void k_fused(const float* __restrict__ x, const float* __restrict__ b_fc,
             float* __restrict__ out, int n, int tiles) {
    extern __shared__ float sm[];
    float* Mts  = sm;                     // 16384  [k][f][o]
    float* rT   = Mts + KK * FF * FF;     // 64*68  [f][n]
    float* wqs  = rT + FF * 68;           // 256
    float* mbs  = wqs + KK * FF;          // 256
    float* bfcs = mbs + KK * FF;          // 64
    float* qbs  = bfcs + FF;              // 4
    float* slog = qbs + KK;               // 256  [k][64]
    int t = threadIdx.x;
    for (int i = t; i < KK * FF * FF; i += 256) Mts[i] = g_Mt[i];
    wqs[t] = g_wq[t];
    mbs[t] = g_mb[t];
    if (t < FF) bfcs[t] = b_fc[t];
    if (t < KK) qbs[t] = g_qb[t];
    __syncthreads();
    int tx = t & 15, ty = t >> 4;
    for (int tile = blockIdx.x; tile < tiles; tile += gridDim.x) {
        int nb = tile * 64;
        float4 acc[KK][4];
        #pragma unroll
        for (int k = 0; k < KK; k++)
            #pragma unroll
            for (int i = 0; i < 4; i++) acc[k][i] = make_float4(0.f, 0.f, 0.f, 0.f);
        #pragma unroll
        for (int k = 0; k < KK; k++) {
            const float* src = (k == 0) ? x : &g_xs[k - 1][0];
            __syncthreads();   // protect rT (and slog of previous tile) reuse
            for (int i = t; i < FF * 64; i += 256) {
                int nn = i >> 6, f = i & 63;
                float v = (nb + nn < n) ? src[(size_t)(nb + nn) * FF + f] : 0.f;
                rT[f * 68 + nn] = v;
            }
            __syncthreads();
            if (t < 64) {
                float s = qbs[k];
                #pragma unroll
                for (int f = 0; f < FF; f++) s += wqs[k * FF + f] * rT[f * 68 + t];
                slog[k * 64 + t] = tanhf(s);
            }
            const float* Mk = Mts + (k << 12) + (tx << 2);
            #pragma unroll
            for (int f = 0; f < FF; f++) {
                float4 a = *(const float4*)(rT + f * 68 + (ty << 2));
                float4 b = *(const float4*)(Mk + (f << 6));
                acc[k][0].x += a.x * b.x; acc[k][0].y += a.x * b.y; acc[k][0].z += a.x * b.z; acc[k][0].w += a.x * b.w;
                acc[k][1].x += a.y * b.x; acc[k][1].y += a.y * b.y; acc[k][1].z += a.y * b.z; acc[k][1].w += a.y * b.w;
                acc[k][2].x += a.z * b.x; acc[k][2].y += a.z * b.y; acc[k][2].z += a.z * b.z; acc[k][2].w += a.z * b.w;
                acc[k][3].x += a.w * b.x; acc[k][3].y += a.w * b.y; acc[k][3].z += a.w * b.z; acc[k][3].w += a.w * b.w;
            }
        }
        __syncthreads();   // slog complete for all k
        #pragma unroll
        for (int i = 0; i < 4; i++) {
            int nn = (ty << 2) + i;
            int node = nb + nn;
            if (node < n) {
                float s0 = slog[nn], s1 = slog[64 + nn], s2 = slog[128 + nn], s3 = slog[192 + nn];
                float m = fmaxf(fmaxf(s0, s1), fmaxf(s2, s3));
                float e0 = __expf(s0 - m), e1 = __expf(s1 - m);
                float e2 = __expf(s2 - m), e3 = __expf(s3 - m);
                float rinv = 1.f / (e0 + e1 + e2 + e3);
                float a0 = e0 * rinv, a1 = e1 * rinv, a2 = e2 * rinv, a3 = e3 * rinv;
                int oc = tx << 2;
                float4 o4;
                o4.x = bfcs[oc + 0]
                     + a0 * (acc[0][i].x + mbs[oc + 0]) + a1 * (acc[1][i].x + mbs[64 + oc + 0])
                     + a2 * (acc[2][i].x + mbs[128 + oc + 0]) + a3 * (acc[3][i].x + mbs[192 + oc + 0]);
                o4.y = bfcs[oc + 1]
                     + a0 * (acc[0][i].y + mbs[oc + 1]) + a1 * (acc[1][i].y + mbs[64 + oc + 1])
                     + a2 * (acc[2][i].y + mbs[128 + oc + 1]) + a3 * (acc[3][i].y + mbs[192 + oc + 1]);
                o4.z = bfcs[oc + 2]
                     + a0 * (acc[0][i].z + mbs[oc + 2]) + a1 * (acc[1][i].z + mbs[64 + oc + 2])
                     + a2 * (acc[2][i].z + mbs[128 + oc + 2]) + a3 * (acc[3][i].z + mbs[192 + oc + 2]);
                o4.w = bfcs[oc + 3]
                     + a0 * (acc[0][i].w + mbs[oc + 3]) + a1 * (acc[1][i].w + mbs[64 + oc + 3])
                     + a2 * (acc[2][i].w + mbs[128 + oc + 3]) + a3 * (acc[3][i].w + mbs[192 + oc + 3]);
                *(float4*)(out + (size_t)node * FF + oc) = o4;
            }
        }
    }
}

extern "C" void kernel_launch(void* const* d_in, const int* in_sizes, int n_in,
                              void* d_out, int out_size) {
    const float* x     = (const float*)d_in[0];
    const int*   ei    = (const int*)d_in[1];
    const float* ew    = (const float*)d_in[2];
    const float* araw  = (const float*)d_in[3];
    const float* W_att = (const float*)d_in[4];
    const float* b_att = (const float*)d_in[5];
    const float* W_fc  = (const float*)d_in[6];
    const float* b_fc  = (const float*)d_in[7];
    float* out = (float*)d_out;

    int n = in_sizes[0] / FF;
    int E = in_sizes[2];

    cudaFuncSetAttribute(k_fused, cudaFuncAttributeMaxDynamicSharedMemorySize,
                         SM_FUSED_FLOATS * sizeof(float));

    int nb_scan = (n + 1023) / 1024;
    int eb = (E + 255) / 256;
    int nb256 = (n + 255) / 256;
    int pull_blocks = (n + 15) / 16;
    int tiles = (n + 63) / 64;
    int fused_blocks = tiles < 296 ? tiles : 296;

    k_coeff<<<1, 256>>>(araw);
    // CSR build
    k_zero_deg<<<nb256, 256>>>(n);
    k_hist<<<eb, 256>>>(ei, E);
    k_scan1<<<nb_scan, 1024>>>(n);
    k_scan2<<<1, 256>>>(nb_scan);
    k_scan3<<<nb_scan, 1024>>>(n);
    k_fill<<<eb, 256>>>(ei, ew, E);
    // fused pull + recurrence + colsums
    k_pull<<<pull_blocks, 256>>>(x, -1,  -1, 0, 1, n, 1);   // L=1
    k_pull<<<pull_blocks, 256>>>(x,  0,  -1, 1, 2, n, 0);   // L=2
    k_pull<<<pull_blocks, 256>>>(x,  1,   0, 2, 3, n, 0);   // L=3
    // attention prep + fused output
    k_prep1<<<16, 256>>>(W_att, W_fc);
    k_prep2<<<1, 256>>>(W_att, b_att, W_fc, n);
    k_fused<<<fused_blocks, 256, SM_FUSED_FLOATS * sizeof(float)>>>(x, b_fc, out, n, tiles);
}